// round 13
// baseline (speedup 1.0000x reference)
#include <cuda_runtime.h>
#include <cuda_bf16.h>

#define SEQ    32768
#define WD     512
#define HID    1024
#define NCTA   64          // CTAs per fold
#define NFOLD  2
#define ARPC   8           // a/p rows per CTA
#define TRPC   16          // t rows per CTA
#define THREADS 256

typedef unsigned long long ull;

// Packed tag-embedded exchange slots: (tag<<32)|value_bits, 8B stride.
__device__ ull g_aslot[NFOLD][WD];
__device__ ull g_uslot[NFOLD][HID];
__device__ ull g_pslot[NFOLD][WD];
__device__ unsigned int g_epoch_base;   // bumped once per launch by CTA 0

__device__ __forceinline__ ull ldr64(const ull* p) {
    ull v; asm volatile("ld.relaxed.gpu.global.b64 %0, [%1];" : "=l"(v) : "l"(p) : "memory");
    return v;
}
__device__ __forceinline__ void str64(ull* p, ull v) {
    asm volatile("st.relaxed.gpu.global.b64 [%0], %1;" :: "l"(p), "l"(v) : "memory");
}
__device__ __forceinline__ ull pack(unsigned tag, float v) {
    return ((ull)tag << 32) | (ull)__float_as_uint(v);
}
__device__ __forceinline__ bool rdy(ull v, unsigned want) {
    return (int)((unsigned)(v >> 32) - want) >= 0;
}
__device__ __forceinline__ float fval(ull v) { return __uint_as_float((unsigned)v); }

// tanh with ~1e-7 abs error: 1 - 2/(e^{2x}+1)
__device__ __forceinline__ float ftanh(float x) {
    float e = __expf(2.0f * x);
    return 1.0f - __fdividef(2.0f, e + 1.0f);
}
__device__ __forceinline__ float dot4(float4 w, float4 h) {
    return w.x*h.x + w.y*h.y + w.z*h.z + w.w*h.w;
}

struct Smem {
    float p_s[WD];
    float x_s[2][WD];     // double-buffered x
    float a_s[WD];
    float u_s[HID];       // reused for [p0;p1] in the epilogue
    float lgst[8];
};

__global__ void __launch_bounds__(THREADS, 1)
rnn_fold_kernel(const float* __restrict__ input,
                const float* __restrict__ input2,
                const float* __restrict__ W1g, const float* __restrict__ b1g,
                const float* __restrict__ W2g, const float* __restrict__ b2g,
                const float* __restrict__ W3g, const float* __restrict__ b3g,
                const float* __restrict__ W4g, const float* __restrict__ b4g,
                float* __restrict__ out)
{
    __shared__ Smem s;

    const int tid  = threadIdx.x;
    const int lane = tid & 31;
    const int warp = tid >> 5;        // 0..7
    const int cta  = blockIdx.x;
    const int fold = cta / NCTA;
    const int k    = cta % NCTA;
    const float* xsrc = (fold == 0) ? input : input2;

    const int arow0 = k * ARPC;       // global a/p row base
    const int trow0 = k * TRPC;       // global t row base

    const int row16 = (warp << 1) | (lane >> 4);   // local t-row (0..15)
    const int lg16  = lane & 15;

    // ---------------- weights -> registers ----------------
    float4 w1reg[8], w2reg[8], w3reg[8];
    {
        const float4* w1row = reinterpret_cast<const float4*>(W1g + (size_t)(arow0 + warp) * HID);
        const float4* w3row = reinterpret_cast<const float4*>(W3g + (size_t)(arow0 + warp) * HID);
        #pragma unroll
        for (int q = 0; q < 8; ++q) {
            w1reg[q] = w1row[lane + 32 * q];
            w3reg[q] = w3row[lane + 32 * q];
        }
        const float4* w2row = reinterpret_cast<const float4*>(W2g + (size_t)(trow0 + row16) * WD);
        #pragma unroll
        for (int q = 0; q < 8; ++q) w2reg[q] = w2row[lg16 + 16 * q];
    }
    const float b1r = b1g[arow0 + warp];
    const float b3r = b3g[arow0 + warp];
    const float b2r = b2g[trow0 + row16];

    // initial vectors: p0 = x[0], x buffer 1 = x[1]
    reinterpret_cast<float2*>(s.p_s)[tid]    = reinterpret_cast<const float2*>(xsrc)[tid];
    reinterpret_cast<float2*>(s.x_s[1])[tid] = reinterpret_cast<const float2*>(xsrc + WD)[tid];

    unsigned int base;
    asm volatile("ld.relaxed.gpu.global.u32 %0, [%1];" : "=r"(base) : "l"(&g_epoch_base) : "memory");

    // 2-step-ahead x prefetch: xn holds x[i+1] at the top of iteration i.
    float2 xn = make_float2(0.f, 0.f);
    if (2 < SEQ) xn = __ldcg(reinterpret_cast<const float2*>(xsrc + 2 * WD) + tid);
    __syncthreads();

    // xacc for step 1: per-lane partial of (W1 x-half) . x[1]
    float xacc = 0.0f;
    {
        const float4* xx = reinterpret_cast<const float4*>(s.x_s[1]);
        #pragma unroll
        for (int q = 0; q < 4; ++q) xacc += dot4(w1reg[4 + q], xx[lane + 32 * q]);
    }

    for (int i = 1; i < SEQ; ++i) {
        const int buf = i & 1;
        const unsigned t1 = base + 3u * (unsigned)(i - 1) + 1u;
        const bool hasx = (i + 1 < SEQ);

        // ---- stage 1 (critical path = p-half only, 2 FFMA chains) ----
        {
            const float4* pp = reinterpret_cast<const float4*>(s.p_s);
            float accA = xacc, accB = 0.f;
            accA += dot4(w1reg[0], pp[lane]);
            accB += dot4(w1reg[1], pp[lane + 32]);
            accA += dot4(w1reg[2], pp[lane + 64]);
            accB += dot4(w1reg[3], pp[lane + 96]);
            float acc = accA + accB;
            #pragma unroll
            for (int o = 16; o > 0; o >>= 1) acc += __shfl_xor_sync(0xffffffffu, acc, o);
            if (lane == 0)
                str64(&g_aslot[fold][arow0 + warp], pack(t1, fmaxf(acc + b1r, 0.0f)));
        }

        // ---- a-gather: issue first sweep IMMEDIATELY, shadow work after ----
        const ull* a0 = &g_aslot[fold][2 * tid];
        ull va0 = ldr64(a0), va1 = ldr64(a0 + 1);

        // shadow: stash x[i+1] (loaded 1 full step ago — certainly arrived),
        // then fire the LDG for x[i+2] (consumed 2 steps from now)
        if (hasx) reinterpret_cast<float2*>(s.x_s[buf ^ 1])[tid] = xn;
        if (i + 2 < SEQ) xn = __ldcg(reinterpret_cast<const float2*>(xsrc + (size_t)(i + 2) * WD) + tid);

        while (!(rdy(va0, t1) && rdy(va1, t1))) { va0 = ldr64(a0); va1 = ldr64(a0 + 1); }
        reinterpret_cast<float2*>(s.a_s)[tid] = make_float2(fval(va0), fval(va1));
        __syncthreads();

        // ---- stage 2: u-row = tanh(W2.a + b2) (2 FFMA chains) ----
        {
            const float4* aa = reinterpret_cast<const float4*>(s.a_s);
            float accA = 0.f, accB = 0.f;
            #pragma unroll
            for (int q = 0; q < 8; q += 2) {
                accA += dot4(w2reg[q],     aa[lg16 + 16 * q]);
                accB += dot4(w2reg[q + 1], aa[lg16 + 16 * (q + 1)]);
            }
            float acc = accA + accB;
            #pragma unroll
            for (int o = 8; o > 0; o >>= 1) acc += __shfl_xor_sync(0xffffffffu, acc, o);
            if (lg16 == 0)
                str64(&g_uslot[fold][trow0 + row16], pack(t1 + 1u, ftanh(acc + b2r)));
        }

        // ---- u-gather: issue first sweep IMMEDIATELY, xacc in its shadow ----
        const ull* u0 = &g_uslot[fold][2 * tid];
        const ull* u1 = &g_uslot[fold][512 + 2 * tid];
        ull vu0 = ldr64(u0), vu1 = ldr64(u0 + 1), vu2 = ldr64(u1), vu3 = ldr64(u1 + 1);

        // shadow: xacc for NEXT step from the freshly stashed buffer
        // (stash happened before the a-gather __syncthreads above)
        if (hasx) {
            const float4* xx = reinterpret_cast<const float4*>(s.x_s[buf ^ 1]);
            float xa = 0.f, xb = 0.f;
            xa += dot4(w1reg[4], xx[lane]);
            xb += dot4(w1reg[5], xx[lane + 32]);
            xa += dot4(w1reg[6], xx[lane + 64]);
            xb += dot4(w1reg[7], xx[lane + 96]);
            xacc = xa + xb;
        }

        while (!(rdy(vu0, t1 + 1u) && rdy(vu1, t1 + 1u) && rdy(vu2, t1 + 1u) && rdy(vu3, t1 + 1u))) {
            vu0 = ldr64(u0); vu1 = ldr64(u0 + 1); vu2 = ldr64(u1); vu3 = ldr64(u1 + 1);
        }
        reinterpret_cast<float2*>(s.u_s)[tid]       = make_float2(fval(vu0), fval(vu1));
        reinterpret_cast<float2*>(s.u_s + 512)[tid] = make_float2(fval(vu2), fval(vu3));
        __syncthreads();

        // ---- stage 3: p-row = tanh(W3.u + b3) (2 FFMA chains) ----
        {
            const float4* uu = reinterpret_cast<const float4*>(s.u_s);
            float accA = 0.f, accB = 0.f;
            #pragma unroll
            for (int q = 0; q < 8; q += 2) {
                accA += dot4(w3reg[q],     uu[lane + 32 * q]);
                accB += dot4(w3reg[q + 1], uu[lane + 32 * (q + 1)]);
            }
            float acc = accA + accB;
            #pragma unroll
            for (int o = 16; o > 0; o >>= 1) acc += __shfl_xor_sync(0xffffffffu, acc, o);
            if (lane == 0)
                str64(&g_pslot[fold][arow0 + warp], pack(t1 + 2u, ftanh(acc + b3r)));
        }

        // ---- p-gather: issue sweep immediately ----
        if (i < SEQ - 1) {
            const ull* p0 = &g_pslot[fold][2 * tid];
            ull vp0 = ldr64(p0), vp1 = ldr64(p0 + 1);
            while (!(rdy(vp0, t1 + 2u) && rdy(vp1, t1 + 2u))) { vp0 = ldr64(p0); vp1 = ldr64(p0 + 1); }
            reinterpret_cast<float2*>(s.p_s)[tid] = make_float2(fval(vp0), fval(vp1));
            __syncthreads();
        }
    }

    // ---------------- fused epilogue: CTA 0 gathers both folds' final p ----------------
    if (cta == 0) {
        const unsigned tfin = base + 3u * (unsigned)(SEQ - 2) + 3u;
        {
            const ull* q0 = &g_pslot[0][2 * tid];
            const ull* q1 = &g_pslot[1][2 * tid];
            ull v0 = ldr64(q0), v1 = ldr64(q0 + 1), v2 = ldr64(q1), v3 = ldr64(q1 + 1);
            while (!(rdy(v0, tfin) && rdy(v1, tfin) && rdy(v2, tfin) && rdy(v3, tfin))) {
                v0 = ldr64(q0); v1 = ldr64(q0 + 1); v2 = ldr64(q1); v3 = ldr64(q1 + 1);
            }
            reinterpret_cast<float2*>(s.u_s)[tid]       = make_float2(fval(v0), fval(v1));
            reinterpret_cast<float2*>(s.u_s + 512)[tid] = make_float2(fval(v2), fval(v3));
        }
        __syncthreads();

        if (warp < 5) {
            float acc = 0.0f;
            const float* w = W4g + warp * (2 * WD);
            for (int j = lane; j < 2 * WD; j += 32) acc += w[j] * s.u_s[j];
            #pragma unroll
            for (int o = 16; o > 0; o >>= 1) acc += __shfl_down_sync(0xffffffffu, acc, o);
            if (lane == 0) s.lgst[warp] = acc + b4g[warp];
        }
        __syncthreads();
        if (tid == 0) {
            float m = s.lgst[0];
            #pragma unroll
            for (int c = 1; c < 5; ++c) m = fmaxf(m, s.lgst[c]);
            float ssum = 0.0f;
            #pragma unroll
            for (int c = 0; c < 5; ++c) ssum += expf(s.lgst[c] - m);
            float lse = m + logf(ssum);
            #pragma unroll
            for (int c = 0; c < 5; ++c) out[c] = s.lgst[c] - lse;
            // bump epoch base for the next graph replay (3*SEQ > any tag used)
            unsigned nb = base + 3u * (unsigned)SEQ;
            asm volatile("st.relaxed.gpu.global.u32 [%0], %1;" :: "l"(&g_epoch_base), "r"(nb) : "memory");
        }
    }
}

extern "C" void kernel_launch(void* const* d_in, const int* in_sizes, int n_in,
                              void* d_out, int out_size)
{
    const float* input  = (const float*)d_in[0];
    const float* input2 = (const float*)d_in[1];
    const int off = (n_in >= 11) ? 3 : 2;
    const float* W1 = (const float*)d_in[off + 0];
    const float* b1 = (const float*)d_in[off + 1];
    const float* W2 = (const float*)d_in[off + 2];
    const float* b2 = (const float*)d_in[off + 3];
    const float* W3 = (const float*)d_in[off + 4];
    const float* b3 = (const float*)d_in[off + 5];
    const float* W4 = (const float*)d_in[off + 6];
    const float* b4 = (const float*)d_in[off + 7];

    rnn_fold_kernel<<<NFOLD * NCTA, THREADS>>>(
        input, input2, W1, b1, W2, b2, W3, b3, W4, b4, (float*)d_out);
}